// round 2
// baseline (speedup 1.0000x reference)
#include <cuda_runtime.h>

#define BATCH 2
#define SEQ   2048
#define EMB   1024
#define NH    16
#define HD    64
#define MROWS (BATCH*SEQ)   // 4096

// Scratch (static device globals — allocation guards forbid cudaMalloc)
__device__ float g_qp[MROWS * EMB];
__device__ float g_kp[MROWS * EMB];
__device__ float g_vp[MROWS * EMB];
__device__ float g_ctx[MROWS * EMB];

// ---------------------------------------------------------------------------
// SGEMM: C[M,N] = A[M,K] @ B[K,N], all row-major. M%128==0, N%128==0, K%16==0.
// 128x128 block tile, BK=16, 8x8 per thread, 256 threads.
// ---------------------------------------------------------------------------
__global__ __launch_bounds__(256) void sgemm128(
    const float* __restrict__ A, const float* __restrict__ B,
    float* __restrict__ C, int M, int N, int K)
{
    __shared__ float As[16][132];   // padded: conflict-free transposed store
    __shared__ float Bs[16][128];

    const int tid = threadIdx.x;
    const int bx = blockIdx.x, by = blockIdx.y;
    const int ty = tid >> 4;        // 0..15
    const int tx = tid & 15;        // 0..15

    // A loader: float4 along K, transpose into As
    const int aRow = tid >> 2;          // 0..63
    const int aCol = (tid & 3) * 4;     // 0,4,8,12
    // B loader: float4 along N
    const int bRow = tid >> 5;          // 0..7
    const int bCol = (tid & 31) * 4;    // 0..124

    const float* Ab = A + (size_t)(by * 128) * K;
    const float* Bb = B + bx * 128;

    float acc[8][8] = {};

    for (int k0 = 0; k0 < K; k0 += 16) {
        #pragma unroll
        for (int r = 0; r < 128; r += 64) {
            float4 v = *(const float4*)(Ab + (size_t)(aRow + r) * K + k0 + aCol);
            As[aCol + 0][aRow + r] = v.x;
            As[aCol + 1][aRow + r] = v.y;
            As[aCol + 2][aRow + r] = v.z;
            As[aCol + 3][aRow + r] = v.w;
        }
        #pragma unroll
        for (int r = 0; r < 16; r += 8) {
            *(float4*)(&Bs[bRow + r][bCol]) =
                *(const float4*)(Bb + (size_t)(k0 + bRow + r) * N + bCol);
        }
        __syncthreads();

        #pragma unroll
        for (int kk = 0; kk < 16; kk++) {
            float ra[8], rb[8];
            #pragma unroll
            for (int i = 0; i < 8; i++) ra[i] = As[kk][ty * 8 + i];
            #pragma unroll
            for (int j = 0; j < 8; j++) rb[j] = Bs[kk][tx * 8 + j];
            #pragma unroll
            for (int i = 0; i < 8; i++)
                #pragma unroll
                for (int j = 0; j < 8; j++)
                    acc[i][j] += ra[i] * rb[j];
        }
        __syncthreads();
    }

    float* Cb = C + (size_t)(by * 128 + ty * 8) * N + bx * 128 + tx * 8;
    #pragma unroll
    for (int i = 0; i < 8; i++) {
        *(float4*)(Cb + (size_t)i * N)     = make_float4(acc[i][0], acc[i][1], acc[i][2], acc[i][3]);
        *(float4*)(Cb + (size_t)i * N + 4) = make_float4(acc[i][4], acc[i][5], acc[i][6], acc[i][7]);
    }
}

// ---------------------------------------------------------------------------
// Flash attention, fp32. Block = 64 queries for one (b,h). KV tile = 32.
// Online softmax. Q pre-scaled by 1/sqrt(D).
// smem: ~43 KB (static, <48 KB so no capture-unsafe attribute calls needed).
// ---------------------------------------------------------------------------
#define QT 64
#define KT 32
#define QP 68   // pitch (floats) for Q/K/V tiles: 16B-aligned float4 rows, scrambles banks

__global__ __launch_bounds__(256) void flash_attn(
    const float* __restrict__ Qp, const float* __restrict__ Kp,
    const float* __restrict__ Vp, float* __restrict__ Ctx)
{
    __shared__ float Qs[QT][QP];
    __shared__ float Ks[KT][QP];
    __shared__ float Vs[KT][QP];
    __shared__ float Ps[QT][33];
    __shared__ float m_s[QT], l_s[QT], alpha_s[QT];

    const int tid = threadIdx.x;
    const int qt = blockIdx.x, h = blockIdx.y, b = blockIdx.z;
    const int q0 = qt * QT;
    const int ty = tid >> 4;      // 0..15
    const int tx = tid & 15;      // 0..15
    const float scale = 0.125f;   // 1/sqrt(64)

    // Load Q tile [64 x 64], scaled
    {
        const int row = tid >> 4;          // 0..15
        const int c4  = (tid & 15) * 4;    // 0..60
        for (int r = row; r < QT; r += 16) {
            float4 v = *(const float4*)(Qp + ((size_t)(b * SEQ + q0 + r)) * EMB + h * HD + c4);
            v.x *= scale; v.y *= scale; v.z *= scale; v.w *= scale;
            *(float4*)(&Qs[r][c4]) = v;
        }
    }
    if (tid < QT) { m_s[tid] = -1e30f; l_s[tid] = 0.f; }

    float O[4][4] = {};
    const int r0 = ty * 4;      // 4 query rows
    const int c0 = tx * 2;      // 2 key cols (scores)
    const int d0 = tx * 4;      // 4 head dims (output)

    for (int j0 = 0; j0 < SEQ; j0 += KT) {
        __syncthreads();   // prev iter's PV reads of Ks/Vs/Ps done before overwrite
        // Load K,V tiles [32 x 64]
        {
            const int row = tid >> 4;
            const int c4  = (tid & 15) * 4;
            for (int r = row; r < KT; r += 16) {
                size_t gi = ((size_t)(b * SEQ + j0 + r)) * EMB + h * HD + c4;
                *(float4*)(&Ks[r][c4]) = *(const float4*)(Kp + gi);
                *(float4*)(&Vs[r][c4]) = *(const float4*)(Vp + gi);
            }
        }
        __syncthreads();

        // S = Qs @ Ks^T : each thread 4 rows x 2 cols
        float s[4][2] = {};
        #pragma unroll 4
        for (int d = 0; d < HD; d += 4) {
            float4 qv[4], kv[2];
            #pragma unroll
            for (int i = 0; i < 4; i++) qv[i] = *(const float4*)(&Qs[r0 + i][d]);
            #pragma unroll
            for (int j = 0; j < 2; j++) kv[j] = *(const float4*)(&Ks[c0 + j][d]);
            #pragma unroll
            for (int i = 0; i < 4; i++)
                #pragma unroll
                for (int j = 0; j < 2; j++)
                    s[i][j] += qv[i].x * kv[j].x + qv[i].y * kv[j].y
                             + qv[i].z * kv[j].z + qv[i].w * kv[j].w;
        }
        #pragma unroll
        for (int i = 0; i < 4; i++)
            #pragma unroll
            for (int j = 0; j < 2; j++)
                Ps[r0 + i][c0 + j] = s[i][j];
        __syncthreads();

        // Online softmax: 64 threads (2 warps), one per query row.
        if (tid < QT) {
            const int r = tid;
            float mo = m_s[r];
            float mx = mo;
            #pragma unroll 8
            for (int c = 0; c < KT; c++) mx = fmaxf(mx, Ps[r][c]);
            float a = __expf(mo - mx);
            float sum = 0.f;
            #pragma unroll 8
            for (int c = 0; c < KT; c++) {
                float p = __expf(Ps[r][c] - mx);
                Ps[r][c] = p;
                sum += p;
            }
            l_s[r] = l_s[r] * a + sum;
            m_s[r] = mx;
            alpha_s[r] = a;
        }
        __syncthreads();

        // O = O*alpha + P @ V : each thread 4 rows x 4 dims
        float al[4];
        #pragma unroll
        for (int i = 0; i < 4; i++) al[i] = alpha_s[r0 + i];
        #pragma unroll
        for (int i = 0; i < 4; i++)
            #pragma unroll
            for (int j = 0; j < 4; j++)
                O[i][j] *= al[i];

        #pragma unroll 8
        for (int c = 0; c < KT; c++) {
            float p[4];
            #pragma unroll
            for (int i = 0; i < 4; i++) p[i] = Ps[r0 + i][c];
            float4 vv = *(const float4*)(&Vs[c][d0]);
            #pragma unroll
            for (int i = 0; i < 4; i++) {
                O[i][0] += p[i] * vv.x;
                O[i][1] += p[i] * vv.y;
                O[i][2] += p[i] * vv.z;
                O[i][3] += p[i] * vv.w;
            }
        }
    }

    // Epilogue: normalize, write to ctx in [B,S,E] layout
    #pragma unroll
    for (int i = 0; i < 4; i++) {
        float linv = 1.0f / l_s[r0 + i];
        float4 o = make_float4(O[i][0] * linv, O[i][1] * linv, O[i][2] * linv, O[i][3] * linv);
        *(float4*)(Ctx + ((size_t)(b * SEQ + q0 + r0 + i)) * EMB + h * HD + d0) = o;
    }
}

// ---------------------------------------------------------------------------
extern "C" void kernel_launch(void* const* d_in, const int* in_sizes, int n_in,
                              void* d_out, int out_size)
{
    const float* Q  = (const float*)d_in[0];
    const float* K  = (const float*)d_in[1];
    const float* V  = (const float*)d_in[2];
    const float* Wq = (const float*)d_in[3];
    const float* Wk = (const float*)d_in[4];
    const float* Wv = (const float*)d_in[5];
    const float* Wo = (const float*)d_in[6];
    float* out = (float*)d_out;

    // Resolve scratch symbol addresses once (idempotent; no work enqueued,
    // safe both outside and inside graph capture).
    static float *qp = nullptr, *kp = nullptr, *vp = nullptr, *ctx = nullptr;
    if (qp == nullptr) {
        cudaGetSymbolAddress((void**)&qp,  g_qp);
        cudaGetSymbolAddress((void**)&kp,  g_kp);
        cudaGetSymbolAddress((void**)&vp,  g_vp);
        cudaGetSymbolAddress((void**)&ctx, g_ctx);
    }

    dim3 gb(EMB / 128, MROWS / 128);    // (8, 32)
    sgemm128<<<gb, 256>>>(Q, Wq, qp, MROWS, EMB, EMB);
    sgemm128<<<gb, 256>>>(K, Wk, kp, MROWS, EMB, EMB);
    sgemm128<<<gb, 256>>>(V, Wv, vp, MROWS, EMB, EMB);

    dim3 ga(SEQ / QT, NH, BATCH);       // (32, 16, 2)
    flash_attn<<<ga, 256>>>(qp, kp, vp, ctx);

    sgemm128<<<gb, 256>>>(ctx, Wo, out, MROWS, EMB, EMB);
}

// round 6
// speedup vs baseline: 1.3012x; 1.3012x over previous
#include <cuda_runtime.h>
#include <cuda_bf16.h>
#include <cstdint>

#define BATCH 2
#define SEQ   2048
#define EMB   1024
#define NH    16
#define HD    64
#define MROWS (BATCH*SEQ)   // 4096

// ---------------------------------------------------------------------------
// Scratch (static device globals — allocation guards forbid cudaMalloc)
// ---------------------------------------------------------------------------
__device__ float g_qp[MROWS * EMB];
__device__ float g_kp[MROWS * EMB];
__device__ float g_vp[MROWS * EMB];
__device__ float g_ctx[MROWS * EMB];
// bf16 hi/lo splits of activations, [M][K]
__device__ __nv_bfloat16 g_qh[MROWS * EMB], g_ql[MROWS * EMB];
__device__ __nv_bfloat16 g_kh[MROWS * EMB], g_kl[MROWS * EMB];
__device__ __nv_bfloat16 g_vh[MROWS * EMB], g_vl[MROWS * EMB];
__device__ __nv_bfloat16 g_ch[MROWS * EMB], g_cl[MROWS * EMB];
// transposed + split weights, [N][K] layout (K contiguous)
__device__ __nv_bfloat16 g_wqh[EMB * EMB], g_wql[EMB * EMB];
__device__ __nv_bfloat16 g_wkh[EMB * EMB], g_wkl[EMB * EMB];
__device__ __nv_bfloat16 g_wvh[EMB * EMB], g_wvl[EMB * EMB];
__device__ __nv_bfloat16 g_woh[EMB * EMB], g_wol[EMB * EMB];

// ---------------------------------------------------------------------------
// Helpers
// ---------------------------------------------------------------------------
__device__ __forceinline__ uint32_t smem_u32(const void* p) {
    uint32_t a;
    asm("{ .reg .u64 t; cvta.to.shared.u64 t, %1; cvt.u32.u64 %0, t; }" : "=r"(a) : "l"(p));
    return a;
}

#define CP_ASYNC16(dst, src) \
    asm volatile("cp.async.cg.shared.global [%0], [%1], 16;" :: "r"((uint32_t)(dst)), "l"(src))
#define CP_COMMIT() asm volatile("cp.async.commit_group;" ::: "memory")
#define CP_WAIT0()  asm volatile("cp.async.wait_group 0;" ::: "memory")

// mma.sync m16n8k16 bf16 -> f32 (sm_80+, valid on compute_100)
__device__ __forceinline__ void mma16816(float* c, const uint32_t* a, const uint32_t* b) {
    asm volatile(
        "mma.sync.aligned.m16n8k16.row.col.f32.bf16.bf16.f32 "
        "{%0,%1,%2,%3}, {%4,%5,%6,%7}, {%8,%9}, {%0,%1,%2,%3};"
        : "+f"(c[0]), "+f"(c[1]), "+f"(c[2]), "+f"(c[3])
        : "r"(a[0]), "r"(a[1]), "r"(a[2]), "r"(a[3]), "r"(b[0]), "r"(b[1]));
}

// split a float into bf16 hi + bf16 lo (lo = bf16(x - float(hi)))
__device__ __forceinline__ void split1(float x, __nv_bfloat16& h, __nv_bfloat16& l) {
    h = __float2bfloat16_rn(x);
    l = __float2bfloat16_rn(x - __bfloat162float(h));
}
__device__ __forceinline__ uint32_t pack2(__nv_bfloat16 a, __nv_bfloat16 b) {
    return (uint32_t)__bfloat16_as_ushort(a) | ((uint32_t)__bfloat16_as_ushort(b) << 16);
}

// ---------------------------------------------------------------------------
// Pre-pass 1: elementwise bf16 hi/lo split (float4 in, uint2 out)
// ---------------------------------------------------------------------------
__global__ void split_bf16(const float* __restrict__ x, __nv_bfloat16* __restrict__ hi,
                           __nv_bfloat16* __restrict__ lo, int n4) {
    int i = blockIdx.x * blockDim.x + threadIdx.x;
    if (i >= n4) return;
    float4 v = ((const float4*)x)[i];
    __nv_bfloat16 h0, h1, h2, h3, l0, l1, l2, l3;
    split1(v.x, h0, l0); split1(v.y, h1, l1);
    split1(v.z, h2, l2); split1(v.w, h3, l3);
    ((uint2*)hi)[i] = make_uint2(pack2(h0, h1), pack2(h2, h3));
    ((uint2*)lo)[i] = make_uint2(pack2(l0, l1), pack2(l2, l3));
}

// ---------------------------------------------------------------------------
// Pre-pass 2: W[K][N] (N contiguous) -> Wt hi/lo [N][K] (K contiguous), bf16
// ---------------------------------------------------------------------------
__global__ void transpose_split(const float* __restrict__ W,
                                __nv_bfloat16* __restrict__ Thi,
                                __nv_bfloat16* __restrict__ Tlo) {
    __shared__ float t[32][33];
    int x = blockIdx.x * 32 + threadIdx.x;   // n
    int y = blockIdx.y * 32 + threadIdx.y;   // k
    #pragma unroll
    for (int i = 0; i < 32; i += 8)
        t[threadIdx.y + i][threadIdx.x] = W[(size_t)(y + i) * EMB + x];
    __syncthreads();
    int nx = blockIdx.y * 32 + threadIdx.x;  // k
    int ny = blockIdx.x * 32 + threadIdx.y;  // n
    #pragma unroll
    for (int i = 0; i < 32; i += 8) {
        float v = t[threadIdx.x][threadIdx.y + i];
        __nv_bfloat16 h, l;
        split1(v, h, l);
        Thi[(size_t)(ny + i) * EMB + nx] = h;
        Tlo[(size_t)(ny + i) * EMB + nx] = l;
    }
}

// ---------------------------------------------------------------------------
// mma.sync 3x-bf16 GEMM: C[M,N] = (Ahi+Alo)[M,K] @ (Bhi+Blo)[N,K]^T
// Block 128x128, BK=32, 256 threads (8 warps, 2x4, warp tile 64x32).
// SMEM: 4 tiles of 128 rows x 20 words (16 data + 4 pad) = 40960 B STATIC
// (<48 KB: no cudaFuncSetAttribute, no dynamic smem — deliberately matches
// the envelope of the round-2 kernel that is known to run in this harness).
// Single-stage cp.async (load -> sync -> compute); pipelining deferred.
// ---------------------------------------------------------------------------
#define TW 20                 // 32-bit words per smem row
#define TILE_W (128 * TW)     // words per tile (2560)

__global__ __launch_bounds__(256) void gemm_bf16x3(
    const __nv_bfloat16* __restrict__ Ahi, const __nv_bfloat16* __restrict__ Alo,
    const __nv_bfloat16* __restrict__ Bhi, const __nv_bfloat16* __restrict__ Blo,
    float* __restrict__ C, int M, int N, int K)
{
    __shared__ uint32_t sm[4 * TILE_W];   // 40960 bytes, static
    const int tid = threadIdx.x;
    const int wid = tid >> 5, lane = tid & 31;
    const int g = lane >> 2, t = lane & 3;
    const int wm = wid & 1, wn = wid >> 1;          // 2 x 4 warp grid
    const int bm = blockIdx.y * 128, bn = blockIdx.x * 128;

    const uint32_t sbase = smem_u32(sm);

    // loader: 512 16B-chunks per tile, thread covers rows r0 and r0+64, chunk c0
    const int r0 = tid >> 2, c0 = tid & 3;
    const __nv_bfloat16* gsrc[4] = {
        Ahi + (size_t)bm * K, Alo + (size_t)bm * K,
        Bhi + (size_t)bn * K, Blo + (size_t)bn * K
    };

    float acc[4][4][4] = {};

    const int NS = K / 32;
    for (int s = 0; s < NS; s++) {
        const int k0 = s * 32;
        #pragma unroll
        for (int tile = 0; tile < 4; tile++) {
            const __nv_bfloat16* src = gsrc[tile] + (size_t)r0 * K + k0 + c0 * 8;
            uint32_t d = sbase + (tile * TILE_W + r0 * TW + c0 * 4) * 4;
            CP_ASYNC16(d, src);
            CP_ASYNC16(d + 64 * TW * 4, src + (size_t)64 * K);
        }
        CP_COMMIT();
        CP_WAIT0();
        __syncthreads();

        const uint32_t* As  = sm + 0 * TILE_W;
        const uint32_t* Als = sm + 1 * TILE_W;
        const uint32_t* Bs  = sm + 2 * TILE_W;
        const uint32_t* Bls = sm + 3 * TILE_W;

        #pragma unroll
        for (int kk = 0; kk < 2; kk++) {        // two k16 slices per BK=32
            const int kw = kk * 8;
            uint32_t ah[4][4], al[4][4], bh[4][2], bl[4][2];
            #pragma unroll
            for (int mf = 0; mf < 4; mf++) {
                const int m0 = wm * 64 + mf * 16;
                const int i0 = (m0 + g) * TW + t + kw;
                const int i8 = (m0 + g + 8) * TW + t + kw;
                ah[mf][0] = As[i0];  ah[mf][1] = As[i8];
                ah[mf][2] = As[i0 + 4]; ah[mf][3] = As[i8 + 4];
                al[mf][0] = Als[i0]; al[mf][1] = Als[i8];
                al[mf][2] = Als[i0 + 4]; al[mf][3] = Als[i8 + 4];
            }
            #pragma unroll
            for (int nf = 0; nf < 4; nf++) {
                const int n0 = wn * 32 + nf * 8;
                const int j0 = (n0 + g) * TW + t + kw;
                bh[nf][0] = Bs[j0];  bh[nf][1] = Bs[j0 + 4];
                bl[nf][0] = Bls[j0]; bl[nf][1] = Bls[j0 + 4];
            }
            #pragma unroll
            for (int mf = 0; mf < 4; mf++)
                #pragma unroll
                for (int nf = 0; nf < 4; nf++) {
                    mma16816(acc[mf][nf], ah[mf], bh[nf]);
                    mma16816(acc[mf][nf], ah[mf], bl[nf]);
                    mma16816(acc[mf][nf], al[mf], bh[nf]);
                }
        }
        __syncthreads();
    }

    // Epilogue: c0=(g,2t) c1=(g,2t+1) c2=(g+8,2t) c3=(g+8,2t+1)
    #pragma unroll
    for (int mf = 0; mf < 4; mf++) {
        const int m = bm + wm * 64 + mf * 16 + g;
        #pragma unroll
        for (int nf = 0; nf < 4; nf++) {
            const int n = bn + wn * 32 + nf * 8 + 2 * t;
            *(float2*)(C + (size_t)m * N + n)       = make_float2(acc[mf][nf][0], acc[mf][nf][1]);
            *(float2*)(C + (size_t)(m + 8) * N + n) = make_float2(acc[mf][nf][2], acc[mf][nf][3]);
        }
    }
}

// ---------------------------------------------------------------------------
// Flash attention, fp32 (unchanged from round 2 — known-good, 44KB static smem)
// ---------------------------------------------------------------------------
#define QT 64
#define KT 32
#define QP 68

__global__ __launch_bounds__(256) void flash_attn(
    const float* __restrict__ Qp, const float* __restrict__ Kp,
    const float* __restrict__ Vp, float* __restrict__ Ctx)
{
    __shared__ float Qs[QT][QP];
    __shared__ float Ks[KT][QP];
    __shared__ float Vs[KT][QP];
    __shared__ float Ps[QT][33];
    __shared__ float m_s[QT], l_s[QT], alpha_s[QT];

    const int tid = threadIdx.x;
    const int qt = blockIdx.x, h = blockIdx.y, b = blockIdx.z;
    const int q0 = qt * QT;
    const int ty = tid >> 4;
    const int tx = tid & 15;
    const float scale = 0.125f;

    {
        const int row = tid >> 4;
        const int c4  = (tid & 15) * 4;
        for (int r = row; r < QT; r += 16) {
            float4 v = *(const float4*)(Qp + ((size_t)(b * SEQ + q0 + r)) * EMB + h * HD + c4);
            v.x *= scale; v.y *= scale; v.z *= scale; v.w *= scale;
            *(float4*)(&Qs[r][c4]) = v;
        }
    }
    if (tid < QT) { m_s[tid] = -1e30f; l_s[tid] = 0.f; }

    float O[4][4] = {};
    const int r0 = ty * 4;
    const int c0 = tx * 2;
    const int d0 = tx * 4;

    for (int j0 = 0; j0 < SEQ; j0 += KT) {
        __syncthreads();
        {
            const int row = tid >> 4;
            const int c4  = (tid & 15) * 4;
            for (int r = row; r < KT; r += 16) {
                size_t gi = ((size_t)(b * SEQ + j0 + r)) * EMB + h * HD + c4;
                *(float4*)(&Ks[r][c4]) = *(const float4*)(Kp + gi);
                *(float4*)(&Vs[r][c4]) = *(const float4*)(Vp + gi);
            }
        }
        __syncthreads();

        float s[4][2] = {};
        #pragma unroll 4
        for (int d = 0; d < HD; d += 4) {
            float4 qv[4], kv[2];
            #pragma unroll
            for (int i = 0; i < 4; i++) qv[i] = *(const float4*)(&Qs[r0 + i][d]);
            #pragma unroll
            for (int j = 0; j < 2; j++) kv[j] = *(const float4*)(&Ks[c0 + j][d]);
            #pragma unroll
            for (int i = 0; i < 4; i++)
                #pragma unroll
                for (int j = 0; j < 2; j++)
                    s[i][j] += qv[i].x * kv[j].x + qv[i].y * kv[j].y
                             + qv[i].z * kv[j].z + qv[i].w * kv[j].w;
        }
        #pragma unroll
        for (int i = 0; i < 4; i++)
            #pragma unroll
            for (int j = 0; j < 2; j++)
                Ps[r0 + i][c0 + j] = s[i][j];
        __syncthreads();

        if (tid < QT) {
            const int r = tid;
            float mo = m_s[r];
            float mx = mo;
            #pragma unroll 8
            for (int c = 0; c < KT; c++) mx = fmaxf(mx, Ps[r][c]);
            float a = __expf(mo - mx);
            float sum = 0.f;
            #pragma unroll 8
            for (int c = 0; c < KT; c++) {
                float p = __expf(Ps[r][c] - mx);
                Ps[r][c] = p;
                sum += p;
            }
            l_s[r] = l_s[r] * a + sum;
            m_s[r] = mx;
            alpha_s[r] = a;
        }
        __syncthreads();

        float al[4];
        #pragma unroll
        for (int i = 0; i < 4; i++) al[i] = alpha_s[r0 + i];
        #pragma unroll
        for (int i = 0; i < 4; i++)
            #pragma unroll
            for (int j = 0; j < 4; j++)
                O[i][j] *= al[i];

        #pragma unroll 8
        for (int c = 0; c < KT; c++) {
            float p[4];
            #pragma unroll
            for (int i = 0; i < 4; i++) p[i] = Ps[r0 + i][c];
            float4 vv = *(const float4*)(&Vs[c][d0]);
            #pragma unroll
            for (int i = 0; i < 4; i++) {
                O[i][0] += p[i] * vv.x;
                O[i][1] += p[i] * vv.y;
                O[i][2] += p[i] * vv.z;
                O[i][3] += p[i] * vv.w;
            }
        }
    }

    #pragma unroll
    for (int i = 0; i < 4; i++) {
        float linv = 1.0f / l_s[r0 + i];
        float4 o = make_float4(O[i][0] * linv, O[i][1] * linv, O[i][2] * linv, O[i][3] * linv);
        *(float4*)(Ctx + ((size_t)(b * SEQ + q0 + r0 + i)) * EMB + h * HD + d0) = o;
    }
}

// ---------------------------------------------------------------------------
extern "C" void kernel_launch(void* const* d_in, const int* in_sizes, int n_in,
                              void* d_out, int out_size)
{
    const float* Q  = (const float*)d_in[0];
    const float* K  = (const float*)d_in[1];
    const float* V  = (const float*)d_in[2];
    const float* Wq = (const float*)d_in[3];
    const float* Wk = (const float*)d_in[4];
    const float* Wv = (const float*)d_in[5];
    const float* Wo = (const float*)d_in[6];
    float* out = (float*)d_out;

    static float *qp, *kp, *vp, *ctx;
    static __nv_bfloat16 *qh, *ql, *kh, *kl, *vh, *vl, *ch, *cl;
    static __nv_bfloat16 *wqh, *wql, *wkh, *wkl, *wvh, *wvl, *woh, *wol;
    static bool inited = false;
    if (!inited) {
        inited = true;
        cudaGetSymbolAddress((void**)&qp,  g_qp);
        cudaGetSymbolAddress((void**)&kp,  g_kp);
        cudaGetSymbolAddress((void**)&vp,  g_vp);
        cudaGetSymbolAddress((void**)&ctx, g_ctx);
        cudaGetSymbolAddress((void**)&qh,  g_qh); cudaGetSymbolAddress((void**)&ql, g_ql);
        cudaGetSymbolAddress((void**)&kh,  g_kh); cudaGetSymbolAddress((void**)&kl, g_kl);
        cudaGetSymbolAddress((void**)&vh,  g_vh); cudaGetSymbolAddress((void**)&vl, g_vl);
        cudaGetSymbolAddress((void**)&ch,  g_ch); cudaGetSymbolAddress((void**)&cl, g_cl);
        cudaGetSymbolAddress((void**)&wqh, g_wqh); cudaGetSymbolAddress((void**)&wql, g_wql);
        cudaGetSymbolAddress((void**)&wkh, g_wkh); cudaGetSymbolAddress((void**)&wkl, g_wkl);
        cudaGetSymbolAddress((void**)&wvh, g_wvh); cudaGetSymbolAddress((void**)&wvl, g_wvl);
        cudaGetSymbolAddress((void**)&woh, g_woh); cudaGetSymbolAddress((void**)&wol, g_wol);
    }

    const int n4 = MROWS * EMB / 4;
    const int sb = 256, sg = (n4 + sb - 1) / sb;
    split_bf16<<<sg, sb>>>(Q, qh, ql, n4);
    split_bf16<<<sg, sb>>>(K, kh, kl, n4);
    split_bf16<<<sg, sb>>>(V, vh, vl, n4);

    dim3 tb(32, 8), tg(EMB / 32, EMB / 32);
    transpose_split<<<tg, tb>>>(Wq, wqh, wql);
    transpose_split<<<tg, tb>>>(Wk, wkh, wkl);
    transpose_split<<<tg, tb>>>(Wv, wvh, wvl);
    transpose_split<<<tg, tb>>>(Wo, woh, wol);

    dim3 gg(EMB / 128, MROWS / 128);   // (8, 32)
    gemm_bf16x3<<<gg, 256>>>(qh, ql, wqh, wql, qp, MROWS, EMB, EMB);
    gemm_bf16x3<<<gg, 256>>>(kh, kl, wkh, wkl, kp, MROWS, EMB, EMB);
    gemm_bf16x3<<<gg, 256>>>(vh, vl, wvh, wvl, vp, MROWS, EMB, EMB);

    dim3 ga(SEQ / QT, NH, BATCH);      // (32, 16, 2)
    flash_attn<<<ga, 256>>>(qp, kp, vp, ctx);

    split_bf16<<<sg, sb>>>(ctx, ch, cl, n4);
    gemm_bf16x3<<<gg, 256>>>(ch, cl, woh, wol, out, MROWS, EMB, EMB);
}

// round 7
// speedup vs baseline: 2.7288x; 2.0971x over previous
#include <cuda_runtime.h>
#include <cuda_bf16.h>
#include <cstdint>

#define BATCH 2
#define SEQ   2048
#define EMB   1024
#define NH    16
#define HD    64
#define MROWS (BATCH*SEQ)   // 4096

// ---------------------------------------------------------------------------
// Scratch (static device globals — allocation guards forbid cudaMalloc)
// ---------------------------------------------------------------------------
// bf16 hi/lo splits of GEMM inputs
__device__ __nv_bfloat16 g_qh[MROWS * EMB], g_ql[MROWS * EMB];
__device__ __nv_bfloat16 g_kh[MROWS * EMB], g_kl[MROWS * EMB];
__device__ __nv_bfloat16 g_vh[MROWS * EMB], g_vl[MROWS * EMB];
// projection outputs, split bf16 [row][EMB] (Q pre-scaled by 0.125)
__device__ __nv_bfloat16 g_qph[MROWS * EMB], g_qpl[MROWS * EMB];
__device__ __nv_bfloat16 g_kph[MROWS * EMB], g_kpl[MROWS * EMB];
__device__ __nv_bfloat16 g_vph[MROWS * EMB], g_vpl[MROWS * EMB];
// V transposed per head: [(b*NH+h)*HD + d][SEQ]
__device__ __nv_bfloat16 g_vth[MROWS * EMB], g_vtl[MROWS * EMB];
// attention output, split bf16 (input to W_o GEMM)
__device__ __nv_bfloat16 g_ch[MROWS * EMB], g_cl[MROWS * EMB];
// transposed + split weights, [N][K] layout (K contiguous)
__device__ __nv_bfloat16 g_wqh[EMB * EMB], g_wql[EMB * EMB];
__device__ __nv_bfloat16 g_wkh[EMB * EMB], g_wkl[EMB * EMB];
__device__ __nv_bfloat16 g_wvh[EMB * EMB], g_wvl[EMB * EMB];
__device__ __nv_bfloat16 g_woh[EMB * EMB], g_wol[EMB * EMB];

// ---------------------------------------------------------------------------
// Helpers
// ---------------------------------------------------------------------------
__device__ __forceinline__ uint32_t smem_u32(const void* p) {
    uint32_t a;
    asm("{ .reg .u64 t; cvta.to.shared.u64 t, %1; cvt.u32.u64 %0, t; }" : "=r"(a) : "l"(p));
    return a;
}

#define CP_ASYNC16(dst, src) \
    asm volatile("cp.async.cg.shared.global [%0], [%1], 16;" :: "r"((uint32_t)(dst)), "l"(src))
#define CP_COMMIT() asm volatile("cp.async.commit_group;" ::: "memory")
#define CP_WAIT0()  asm volatile("cp.async.wait_group 0;" ::: "memory")

// mma.sync m16n8k16 bf16 -> f32 (sm_80+, valid on compute_100)
__device__ __forceinline__ void mma16816(float* c, const uint32_t* a, const uint32_t* b) {
    asm volatile(
        "mma.sync.aligned.m16n8k16.row.col.f32.bf16.bf16.f32 "
        "{%0,%1,%2,%3}, {%4,%5,%6,%7}, {%8,%9}, {%0,%1,%2,%3};"
        : "+f"(c[0]), "+f"(c[1]), "+f"(c[2]), "+f"(c[3])
        : "r"(a[0]), "r"(a[1]), "r"(a[2]), "r"(a[3]), "r"(b[0]), "r"(b[1]));
}

__device__ __forceinline__ void split1(float x, __nv_bfloat16& h, __nv_bfloat16& l) {
    h = __float2bfloat16_rn(x);
    l = __float2bfloat16_rn(x - __bfloat162float(h));
}
__device__ __forceinline__ uint32_t pack2(__nv_bfloat16 a, __nv_bfloat16 b) {
    return (uint32_t)__bfloat16_as_ushort(a) | ((uint32_t)__bfloat16_as_ushort(b) << 16);
}
// split two floats, produce packed hi and packed lo
__device__ __forceinline__ void split_pack2(float x0, float x1, uint32_t& hi, uint32_t& lo) {
    __nv_bfloat16 h0, l0, h1, l1;
    split1(x0, h0, l0); split1(x1, h1, l1);
    hi = pack2(h0, h1); lo = pack2(l0, l1);
}

// ---------------------------------------------------------------------------
// Pre-pass 1: elementwise bf16 hi/lo split (float4 in, uint2 out)
// ---------------------------------------------------------------------------
__global__ void split_bf16(const float* __restrict__ x, __nv_bfloat16* __restrict__ hi,
                           __nv_bfloat16* __restrict__ lo, int n4) {
    int i = blockIdx.x * blockDim.x + threadIdx.x;
    if (i >= n4) return;
    float4 v = ((const float4*)x)[i];
    uint32_t h01, l01, h23, l23;
    split_pack2(v.x, v.y, h01, l01);
    split_pack2(v.z, v.w, h23, l23);
    ((uint2*)hi)[i] = make_uint2(h01, h23);
    ((uint2*)lo)[i] = make_uint2(l01, l23);
}

// ---------------------------------------------------------------------------
// Pre-pass 2: W[K][N] (N contiguous) -> Wt hi/lo [N][K] (K contiguous), bf16
// ---------------------------------------------------------------------------
__global__ void transpose_split(const float* __restrict__ W,
                                __nv_bfloat16* __restrict__ Thi,
                                __nv_bfloat16* __restrict__ Tlo) {
    __shared__ float t[32][33];
    int x = blockIdx.x * 32 + threadIdx.x;   // n
    int y = blockIdx.y * 32 + threadIdx.y;   // k
    #pragma unroll
    for (int i = 0; i < 32; i += 8)
        t[threadIdx.y + i][threadIdx.x] = W[(size_t)(y + i) * EMB + x];
    __syncthreads();
    int nx = blockIdx.y * 32 + threadIdx.x;  // k
    int ny = blockIdx.x * 32 + threadIdx.y;  // n
    #pragma unroll
    for (int i = 0; i < 32; i += 8) {
        float v = t[threadIdx.x][threadIdx.y + i];
        __nv_bfloat16 h, l;
        split1(v, h, l);
        Thi[(size_t)(ny + i) * EMB + nx] = h;
        Tlo[(size_t)(ny + i) * EMB + nx] = l;
    }
}

// ---------------------------------------------------------------------------
// V transpose: vph/vpl [b*S+s][h*64+d] -> vth/vtl [(b*16+h)*64+d][s]
// ---------------------------------------------------------------------------
__global__ void transpose_v(const __nv_bfloat16* __restrict__ vh,
                            const __nv_bfloat16* __restrict__ vl,
                            __nv_bfloat16* __restrict__ th,
                            __nv_bfloat16* __restrict__ tl) {
    __shared__ __nv_bfloat16 a[32][33], c[32][33];
    const int bh = blockIdx.z;               // b*16+h
    const int b = bh >> 4, h = bh & 15;
    const int s0 = blockIdx.x * 32, d0 = blockIdx.y * 32;
    const int tx = threadIdx.x, ty = threadIdx.y;    // 32 x 8
    #pragma unroll
    for (int i = 0; i < 32; i += 8) {
        size_t src = (size_t)(b * SEQ + s0 + ty + i) * EMB + h * HD + d0 + tx;
        a[ty + i][tx] = vh[src];
        c[ty + i][tx] = vl[src];
    }
    __syncthreads();
    #pragma unroll
    for (int i = 0; i < 32; i += 8) {
        size_t dst = (size_t)(bh * HD + d0 + ty + i) * SEQ + s0 + tx;
        th[dst] = a[tx][ty + i];
        tl[dst] = c[tx][ty + i];
    }
}

// ---------------------------------------------------------------------------
// mma.sync 3x-bf16 GEMM: C = (Ahi+Alo)[M,K] @ (Bhi+Blo)[N,K]^T
// Block 128x128, BK=32, 256 threads (8 warps 2x4, warp tile 64x32).
// Epilogue: optional fp32 out (Cf) and/or split-bf16 out (Chi/Clo, scaled).
// SMEM: 4 tiles x 128 rows x 20 words = 40960 B static.
// ---------------------------------------------------------------------------
#define TW 20
#define TILE_W (128 * TW)

__global__ __launch_bounds__(256) void gemm_bf16x3(
    const __nv_bfloat16* __restrict__ Ahi, const __nv_bfloat16* __restrict__ Alo,
    const __nv_bfloat16* __restrict__ Bhi, const __nv_bfloat16* __restrict__ Blo,
    float* __restrict__ Cf, __nv_bfloat16* __restrict__ Chi,
    __nv_bfloat16* __restrict__ Clo, float scale, int M, int N, int K)
{
    __shared__ uint32_t sm[4 * TILE_W];
    const int tid = threadIdx.x;
    const int wid = tid >> 5, lane = tid & 31;
    const int g = lane >> 2, t = lane & 3;
    const int wm = wid & 1, wn = wid >> 1;
    const int bm = blockIdx.y * 128, bn = blockIdx.x * 128;

    const uint32_t sbase = smem_u32(sm);
    const int r0 = tid >> 2, c0 = tid & 3;
    const __nv_bfloat16* gsrc[4] = {
        Ahi + (size_t)bm * K, Alo + (size_t)bm * K,
        Bhi + (size_t)bn * K, Blo + (size_t)bn * K
    };

    float acc[4][4][4] = {};

    const int NS = K / 32;
    for (int s = 0; s < NS; s++) {
        const int k0 = s * 32;
        #pragma unroll
        for (int tile = 0; tile < 4; tile++) {
            const __nv_bfloat16* src = gsrc[tile] + (size_t)r0 * K + k0 + c0 * 8;
            uint32_t d = sbase + (tile * TILE_W + r0 * TW + c0 * 4) * 4;
            CP_ASYNC16(d, src);
            CP_ASYNC16(d + 64 * TW * 4, src + (size_t)64 * K);
        }
        CP_COMMIT();
        CP_WAIT0();
        __syncthreads();

        const uint32_t* As  = sm + 0 * TILE_W;
        const uint32_t* Als = sm + 1 * TILE_W;
        const uint32_t* Bs  = sm + 2 * TILE_W;
        const uint32_t* Bls = sm + 3 * TILE_W;

        #pragma unroll
        for (int kk = 0; kk < 2; kk++) {
            const int kw = kk * 8;
            uint32_t ah[4][4], al[4][4], bh[4][2], bl[4][2];
            #pragma unroll
            for (int mf = 0; mf < 4; mf++) {
                const int m0 = wm * 64 + mf * 16;
                const int i0 = (m0 + g) * TW + t + kw;
                const int i8 = (m0 + g + 8) * TW + t + kw;
                ah[mf][0] = As[i0];  ah[mf][1] = As[i8];
                ah[mf][2] = As[i0 + 4]; ah[mf][3] = As[i8 + 4];
                al[mf][0] = Als[i0]; al[mf][1] = Als[i8];
                al[mf][2] = Als[i0 + 4]; al[mf][3] = Als[i8 + 4];
            }
            #pragma unroll
            for (int nf = 0; nf < 4; nf++) {
                const int n0 = wn * 32 + nf * 8;
                const int j0 = (n0 + g) * TW + t + kw;
                bh[nf][0] = Bs[j0];  bh[nf][1] = Bs[j0 + 4];
                bl[nf][0] = Bls[j0]; bl[nf][1] = Bls[j0 + 4];
            }
            #pragma unroll
            for (int mf = 0; mf < 4; mf++)
                #pragma unroll
                for (int nf = 0; nf < 4; nf++) {
                    mma16816(acc[mf][nf], ah[mf], bh[nf]);
                    mma16816(acc[mf][nf], ah[mf], bl[nf]);
                    mma16816(acc[mf][nf], al[mf], bh[nf]);
                }
        }
        __syncthreads();
    }

    #pragma unroll
    for (int mf = 0; mf < 4; mf++) {
        const int m = bm + wm * 64 + mf * 16 + g;
        #pragma unroll
        for (int nf = 0; nf < 4; nf++) {
            const int n = bn + wn * 32 + nf * 8 + 2 * t;
            float v0 = acc[mf][nf][0], v1 = acc[mf][nf][1];
            float v2 = acc[mf][nf][2], v3 = acc[mf][nf][3];
            if (Cf) {
                *(float2*)(Cf + (size_t)m * N + n)       = make_float2(v0, v1);
                *(float2*)(Cf + (size_t)(m + 8) * N + n) = make_float2(v2, v3);
            }
            if (Chi) {
                uint32_t h01, l01, h23, l23;
                split_pack2(v0 * scale, v1 * scale, h01, l01);
                split_pack2(v2 * scale, v3 * scale, h23, l23);
                *(uint32_t*)(Chi + (size_t)m * N + n)       = h01;
                *(uint32_t*)(Clo + (size_t)m * N + n)       = l01;
                *(uint32_t*)(Chi + (size_t)(m + 8) * N + n) = h23;
                *(uint32_t*)(Clo + (size_t)(m + 8) * N + n) = l23;
            }
        }
    }
}

// ---------------------------------------------------------------------------
// Flash attention on mma.sync, 3-term bf16 splits for QK^T and PV.
// Block = 64 queries of one (b,h); 4 warps x 16 rows. KV tile = 32 keys.
// Q frags from global (pre-scaled); K/V tiles staged in smem (~19 KB).
// P stays in registers (S C-frag == PV A-frag layout). Output: split bf16.
// ---------------------------------------------------------------------------
#define FKP 72   // K smem pitch (bf16) -> bank word = g*4+t, conflict-free
#define FVP 40   // VT smem pitch (bf16) -> bank word = g*20+t mod 32, conflict-free

__global__ __launch_bounds__(128) void flash_mma(
    const __nv_bfloat16* __restrict__ Qh, const __nv_bfloat16* __restrict__ Ql,
    const __nv_bfloat16* __restrict__ Kh, const __nv_bfloat16* __restrict__ Kl,
    const __nv_bfloat16* __restrict__ Vth, const __nv_bfloat16* __restrict__ Vtl,
    __nv_bfloat16* __restrict__ Ch, __nv_bfloat16* __restrict__ Cl)
{
    __shared__ __nv_bfloat16 Ksh[32 * FKP], Ksl[32 * FKP];
    __shared__ __nv_bfloat16 Vsh[64 * FVP], Vsl[64 * FVP];

    const int tid = threadIdx.x, wid = tid >> 5, lane = tid & 31;
    const int g = lane >> 2, t = lane & 3;
    const int qt = blockIdx.x, h = blockIdx.y, b = blockIdx.z;
    const int q0 = qt * 64, m0 = wid * 16;

    // --- Q fragments, loaded once from global (already scaled by 1/8) ---
    uint32_t qhf[4][4], qlf[4][4];
    {
        const size_t rbase = (size_t)(b * SEQ + q0 + m0 + g) * EMB + h * HD;
        const __nv_bfloat16* q0h = Qh + rbase;
        const __nv_bfloat16* q8h = q0h + (size_t)8 * EMB;
        const __nv_bfloat16* q0l = Ql + rbase;
        const __nv_bfloat16* q8l = q0l + (size_t)8 * EMB;
        #pragma unroll
        for (int kc = 0; kc < 4; kc++) {
            const int d0 = kc * 16 + 2 * t;
            qhf[kc][0] = *(const uint32_t*)(q0h + d0);
            qhf[kc][1] = *(const uint32_t*)(q8h + d0);
            qhf[kc][2] = *(const uint32_t*)(q0h + d0 + 8);
            qhf[kc][3] = *(const uint32_t*)(q8h + d0 + 8);
            qlf[kc][0] = *(const uint32_t*)(q0l + d0);
            qlf[kc][1] = *(const uint32_t*)(q8l + d0);
            qlf[kc][2] = *(const uint32_t*)(q0l + d0 + 8);
            qlf[kc][3] = *(const uint32_t*)(q8l + d0 + 8);
        }
    }

    float O[8][4] = {};
    float m_g = -1e30f, m_g8 = -1e30f, l_g = 0.f, l_g8 = 0.f;

    // loader assignments
    const int kr = tid >> 2, kc4 = tid & 3;   // K: row kr (0..31), chunks kc4, kc4+4
    const int vd = tid >> 1, vc = tid & 1;    // V: dim row vd (0..63), chunks vc, vc+2
    const __nv_bfloat16* khb = Kh + (size_t)(b * SEQ) * EMB + h * HD;
    const __nv_bfloat16* klb = Kl + (size_t)(b * SEQ) * EMB + h * HD;
    const __nv_bfloat16* vhb = Vth + (size_t)((b * NH + h) * HD) * SEQ;
    const __nv_bfloat16* vlb = Vtl + (size_t)((b * NH + h) * HD) * SEQ;
    const uint32_t sKh = smem_u32(Ksh), sKl = smem_u32(Ksl);
    const uint32_t sVh = smem_u32(Vsh), sVl = smem_u32(Vsl);

    for (int j0 = 0; j0 < SEQ; j0 += 32) {
        // stage K/V tiles
        {
            const __nv_bfloat16* ks = khb + (size_t)(j0 + kr) * EMB + kc4 * 8;
            const __nv_bfloat16* ls = klb + (size_t)(j0 + kr) * EMB + kc4 * 8;
            const uint32_t kd = kr * (FKP * 2) + kc4 * 16;
            CP_ASYNC16(sKh + kd, ks);
            CP_ASYNC16(sKh + kd + 64, ks + 32);
            CP_ASYNC16(sKl + kd, ls);
            CP_ASYNC16(sKl + kd + 64, ls + 32);
            const __nv_bfloat16* vs = vhb + (size_t)vd * SEQ + j0 + vc * 8;
            const __nv_bfloat16* ws = vlb + (size_t)vd * SEQ + j0 + vc * 8;
            const uint32_t vdd = vd * (FVP * 2) + vc * 16;
            CP_ASYNC16(sVh + vdd, vs);
            CP_ASYNC16(sVh + vdd + 32, vs + 16);
            CP_ASYNC16(sVl + vdd, ws);
            CP_ASYNC16(sVl + vdd + 32, ws + 16);
        }
        CP_COMMIT();
        CP_WAIT0();
        __syncthreads();

        // --- S = Q K^T  (64x32 per block, 16x32 per warp) ---
        float s[4][4] = {};
        #pragma unroll
        for (int kc = 0; kc < 4; kc++) {
            uint32_t bh_[4][2], bl_[4][2];
            #pragma unroll
            for (int nf = 0; nf < 4; nf++) {
                const int base = (nf * 8 + g) * FKP + kc * 16 + 2 * t;
                bh_[nf][0] = *(const uint32_t*)(Ksh + base);
                bh_[nf][1] = *(const uint32_t*)(Ksh + base + 8);
                bl_[nf][0] = *(const uint32_t*)(Ksl + base);
                bl_[nf][1] = *(const uint32_t*)(Ksl + base + 8);
            }
            #pragma unroll
            for (int nf = 0; nf < 4; nf++) {
                mma16816(s[nf], qhf[kc], bh_[nf]);
                mma16816(s[nf], qhf[kc], bl_[nf]);
                mma16816(s[nf], qlf[kc], bh_[nf]);
            }
        }

        // --- online softmax (rows g and g+8) ---
        float mx0 = -1e30f, mx8 = -1e30f;
        #pragma unroll
        for (int nf = 0; nf < 4; nf++) {
            mx0 = fmaxf(mx0, fmaxf(s[nf][0], s[nf][1]));
            mx8 = fmaxf(mx8, fmaxf(s[nf][2], s[nf][3]));
        }
        mx0 = fmaxf(mx0, __shfl_xor_sync(0xffffffffu, mx0, 1));
        mx0 = fmaxf(mx0, __shfl_xor_sync(0xffffffffu, mx0, 2));
        mx8 = fmaxf(mx8, __shfl_xor_sync(0xffffffffu, mx8, 1));
        mx8 = fmaxf(mx8, __shfl_xor_sync(0xffffffffu, mx8, 2));
        const float mn_g = fmaxf(m_g, mx0), mn_g8 = fmaxf(m_g8, mx8);
        const float alpha_g = __expf(m_g - mn_g), alpha_g8 = __expf(m_g8 - mn_g8);
        m_g = mn_g; m_g8 = mn_g8;

        float p[4][4];
        float sum0 = 0.f, sum8 = 0.f;
        #pragma unroll
        for (int nf = 0; nf < 4; nf++) {
            p[nf][0] = __expf(s[nf][0] - mn_g);
            p[nf][1] = __expf(s[nf][1] - mn_g);
            p[nf][2] = __expf(s[nf][2] - mn_g8);
            p[nf][3] = __expf(s[nf][3] - mn_g8);
            sum0 += p[nf][0] + p[nf][1];
            sum8 += p[nf][2] + p[nf][3];
        }
        sum0 += __shfl_xor_sync(0xffffffffu, sum0, 1);
        sum0 += __shfl_xor_sync(0xffffffffu, sum0, 2);
        sum8 += __shfl_xor_sync(0xffffffffu, sum8, 1);
        sum8 += __shfl_xor_sync(0xffffffffu, sum8, 2);
        l_g  = l_g  * alpha_g  + sum0;
        l_g8 = l_g8 * alpha_g8 + sum8;

        #pragma unroll
        for (int nf2 = 0; nf2 < 8; nf2++) {
            O[nf2][0] *= alpha_g;  O[nf2][1] *= alpha_g;
            O[nf2][2] *= alpha_g8; O[nf2][3] *= alpha_g8;
        }

        // --- P fragments (S C-frag == PV A-frag layout) ---
        uint32_t pah[2][4], pal[2][4];
        #pragma unroll
        for (int kc2 = 0; kc2 < 2; kc2++) {
            const int nA = 2 * kc2, nB = 2 * kc2 + 1;
            split_pack2(p[nA][0], p[nA][1], pah[kc2][0], pal[kc2][0]);
            split_pack2(p[nA][2], p[nA][3], pah[kc2][1], pal[kc2][1]);
            split_pack2(p[nB][0], p[nB][1], pah[kc2][2], pal[kc2][2]);
            split_pack2(p[nB][2], p[nB][3], pah[kc2][3], pal[kc2][3]);
        }

        // --- O += P V ---
        #pragma unroll
        for (int nf2 = 0; nf2 < 8; nf2++) {
            #pragma unroll
            for (int kc2 = 0; kc2 < 2; kc2++) {
                const int base = (nf2 * 8 + g) * FVP + kc2 * 16 + 2 * t;
                uint32_t vbh[2], vbl[2];
                vbh[0] = *(const uint32_t*)(Vsh + base);
                vbh[1] = *(const uint32_t*)(Vsh + base + 8);
                vbl[0] = *(const uint32_t*)(Vsl + base);
                vbl[1] = *(const uint32_t*)(Vsl + base + 8);
                mma16816(O[nf2], pah[kc2], vbh);
                mma16816(O[nf2], pal[kc2], vbh);
                mma16816(O[nf2], pah[kc2], vbl);
            }
        }
        __syncthreads();   // all reads done before next tile overwrite
    }

    // --- epilogue: normalize, split to bf16 hi/lo ---
    const float li_g = 1.0f / l_g, li_g8 = 1.0f / l_g8;
    const size_t row0 = (size_t)(b * SEQ + q0 + m0 + g) * EMB;
    const size_t row8 = row0 + (size_t)8 * EMB;
    #pragma unroll
    for (int nf2 = 0; nf2 < 8; nf2++) {
        const int col = h * HD + nf2 * 8 + 2 * t;
        uint32_t h01, l01, h23, l23;
        split_pack2(O[nf2][0] * li_g,  O[nf2][1] * li_g,  h01, l01);
        split_pack2(O[nf2][2] * li_g8, O[nf2][3] * li_g8, h23, l23);
        *(uint32_t*)(Ch + row0 + col) = h01;
        *(uint32_t*)(Cl + row0 + col) = l01;
        *(uint32_t*)(Ch + row8 + col) = h23;
        *(uint32_t*)(Cl + row8 + col) = l23;
    }
}

// ---------------------------------------------------------------------------
extern "C" void kernel_launch(void* const* d_in, const int* in_sizes, int n_in,
                              void* d_out, int out_size)
{
    const float* Q  = (const float*)d_in[0];
    const float* K  = (const float*)d_in[1];
    const float* V  = (const float*)d_in[2];
    const float* Wq = (const float*)d_in[3];
    const float* Wk = (const float*)d_in[4];
    const float* Wv = (const float*)d_in[5];
    const float* Wo = (const float*)d_in[6];
    float* out = (float*)d_out;

    static __nv_bfloat16 *qh, *ql, *kh, *kl, *vh, *vl;
    static __nv_bfloat16 *qph, *qpl, *kph, *kpl, *vph, *vpl, *vth, *vtl, *ch, *cl;
    static __nv_bfloat16 *wqh, *wql, *wkh, *wkl, *wvh, *wvl, *woh, *wol;
    static bool inited = false;
    if (!inited) {
        inited = true;
        cudaGetSymbolAddress((void**)&qh,  g_qh);  cudaGetSymbolAddress((void**)&ql,  g_ql);
        cudaGetSymbolAddress((void**)&kh,  g_kh);  cudaGetSymbolAddress((void**)&kl,  g_kl);
        cudaGetSymbolAddress((void**)&vh,  g_vh);  cudaGetSymbolAddress((void**)&vl,  g_vl);
        cudaGetSymbolAddress((void**)&qph, g_qph); cudaGetSymbolAddress((void**)&qpl, g_qpl);
        cudaGetSymbolAddress((void**)&kph, g_kph); cudaGetSymbolAddress((void**)&kpl, g_kpl);
        cudaGetSymbolAddress((void**)&vph, g_vph); cudaGetSymbolAddress((void**)&vpl, g_vpl);
        cudaGetSymbolAddress((void**)&vth, g_vth); cudaGetSymbolAddress((void**)&vtl, g_vtl);
        cudaGetSymbolAddress((void**)&ch,  g_ch);  cudaGetSymbolAddress((void**)&cl,  g_cl);
        cudaGetSymbolAddress((void**)&wqh, g_wqh); cudaGetSymbolAddress((void**)&wql, g_wql);
        cudaGetSymbolAddress((void**)&wkh, g_wkh); cudaGetSymbolAddress((void**)&wkl, g_wkl);
        cudaGetSymbolAddress((void**)&wvh, g_wvh); cudaGetSymbolAddress((void**)&wvl, g_wvl);
        cudaGetSymbolAddress((void**)&woh, g_woh); cudaGetSymbolAddress((void**)&wol, g_wol);
    }

    const int n4 = MROWS * EMB / 4;
    const int sb = 256, sg = (n4 + sb - 1) / sb;
    split_bf16<<<sg, sb>>>(Q, qh, ql, n4);
    split_bf16<<<sg, sb>>>(K, kh, kl, n4);
    split_bf16<<<sg, sb>>>(V, vh, vl, n4);

    dim3 tb(32, 8), tg(EMB / 32, EMB / 32);
    transpose_split<<<tg, tb>>>(Wq, wqh, wql);
    transpose_split<<<tg, tb>>>(Wk, wkh, wkl);
    transpose_split<<<tg, tb>>>(Wv, wvh, wvl);
    transpose_split<<<tg, tb>>>(Wo, woh, wol);

    dim3 gg(EMB / 128, MROWS / 128);   // (8, 32)
    gemm_bf16x3<<<gg, 256>>>(qh, ql, wqh, wql, nullptr, qph, qpl, 0.125f, MROWS, EMB, EMB);
    gemm_bf16x3<<<gg, 256>>>(kh, kl, wkh, wkl, nullptr, kph, kpl, 1.0f,   MROWS, EMB, EMB);
    gemm_bf16x3<<<gg, 256>>>(vh, vl, wvh, wvl, nullptr, vph, vpl, 1.0f,   MROWS, EMB, EMB);

    dim3 vt(SEQ / 32, HD / 32, BATCH * NH);    // (64, 2, 32)
    transpose_v<<<vt, tb>>>(vph, vpl, vth, vtl);

    dim3 ga(SEQ / 64, NH, BATCH);              // (32, 16, 2)
    flash_mma<<<ga, 128>>>(qph, qpl, kph, kpl, vth, vtl, ch, cl);

    gemm_bf16x3<<<gg, 256>>>(ch, cl, woh, wol, out, nullptr, nullptr, 1.0f, MROWS, EMB, EMB);
}